// round 16
// baseline (speedup 1.0000x reference)
#include <cuda_runtime.h>
#include <cuda_fp16.h>
#include <cstdint>

#define B_  2
#define L_  2048
#define D_  1024
#define S_  256
#define V_  32000
#define M_  (B_*L_)     /* 4096 */
#define S2_ (2*S_)      /* 512  */
#define EPS_ 1e-6f

#define CH_ 128
#define CL_ (L_/CH_)    /* 16 */
#define GB_SLICES 16

// ---------------- scratch (__device__ globals; no allocs) ----------------
__device__ __align__(16) float g_ub [M_*S2_];
__device__ float g_endr[B_*CH_*S_];
__device__ float g_endi[B_*CH_*S_];
__device__ float g_incr[B_*CH_*S_];
__device__ float g_inci[B_*CH_*S_];
__device__ float g_gpart[GB_SLICES*V_];
__device__ __align__(1024) __half g_uhi[M_*D_];
__device__ __align__(1024) __half g_ulo[M_*D_];
__device__ __align__(1024) __half g_bchi[D_*S2_];
__device__ __align__(1024) __half g_bclo[D_*S2_];
__device__ __align__(1024) __half g_xchi[M_*S2_];
__device__ __align__(1024) __half g_cchi[S2_*D_];
__device__ __align__(1024) __half g_whi[(size_t)D_*V_];
__device__ __align__(1024) __half g_Ghi[(size_t)S2_*V_];
__device__ float g_gb[V_];

// ---------------- PTX helpers ------------------
__device__ __forceinline__ uint32_t smem_to_u32(const void* p) {
    uint32_t a;
    asm("{ .reg .u64 t; cvta.to.shared.u64 t, %1; cvt.u32.u64 %0, t; }"
        : "=r"(a) : "l"(p));
    return a;
}
__device__ __forceinline__ void cp_async16(uint32_t dst, const void* src) {
    asm volatile("cp.async.cg.shared.global [%0], [%1], 16;"
                 :: "r"(dst), "l"(src) : "memory");
}
#define CP_COMMIT() asm volatile("cp.async.commit_group;" ::: "memory")
#define CP_WAIT(n)  asm volatile("cp.async.wait_group %0;" :: "n"(n) : "memory")

#define LDSM4(r0,r1,r2,r3,a) \
    asm volatile("ldmatrix.sync.aligned.m8n8.x4.shared.b16 {%0,%1,%2,%3}, [%4];" \
        : "=r"(r0), "=r"(r1), "=r"(r2), "=r"(r3) : "r"(a))
#define LDSM4T(r0,r1,r2,r3,a) \
    asm volatile("ldmatrix.sync.aligned.m8n8.x4.trans.shared.b16 {%0,%1,%2,%3}, [%4];" \
        : "=r"(r0), "=r"(r1), "=r"(r2), "=r"(r3) : "r"(a))

#define MMA_F16(d, a0,a1,a2,a3, b0,b1) \
    asm volatile("mma.sync.aligned.m16n8k16.row.col.f32.f16.f16.f32 " \
        "{%0,%1,%2,%3}, {%4,%5,%6,%7}, {%8,%9}, {%0,%1,%2,%3};" \
        : "+f"((d)[0]), "+f"((d)[1]), "+f"((d)[2]), "+f"((d)[3]) \
        : "r"(a0), "r"(a1), "r"(a2), "r"(a3), "r"(b0), "r"(b1))

// fp16-accumulate variant (2x rate); d = 2 regs of f16x2
#define MMA_F16ACC(d, a0,a1,a2,a3, b0,b1) \
    asm volatile("mma.sync.aligned.m16n8k16.row.col.f16.f16.f16.f16 " \
        "{%0,%1}, {%2,%3,%4,%5}, {%6,%7}, {%0,%1};" \
        : "+r"((d)[0]), "+r"((d)[1]) \
        : "r"(a0), "r"(a1), "r"(a2), "r"(a3), "r"(b0), "r"(b1))

__inline__ __device__ float warpSum(float v) {
#pragma unroll
    for (int o = 16; o > 0; o >>= 1) v += __shfl_down_sync(0xffffffffu, v, o);
    return v;
}
__device__ __forceinline__ void split16(float v, __half& h, __half& l) {
    h = __float2half(v);
    l = __float2half(v - __half2float(h));
}

// =========================================================================
// embedding + double RMSNorm -> fp16 hi/lo
// =========================================================================
__global__ void embed_norm_kernel(const int* __restrict__ ids,
                                  const float* __restrict__ emb,
                                  const float* __restrict__ w1,
                                  const float* __restrict__ w2,
                                  __half* __restrict__ uhi,
                                  __half* __restrict__ ulo) {
    int token = blockIdx.x;
    int t = threadIdx.x;
    int id = ids[token];
    const float* e = emb + (size_t)id * D_;

    float v[4]; float ss = 0.f;
#pragma unroll
    for (int i = 0; i < 4; i++) { v[i] = e[t + 256 * i]; ss += v[i] * v[i]; }

    __shared__ float red[8];
    int lane = t & 31, wid = t >> 5;
    float w = warpSum(ss);
    if (lane == 0) red[wid] = w;
    __syncthreads();
    if (wid == 0) {
        float q = (lane < 8) ? red[lane] : 0.f;
        q = warpSum(q);
        if (lane == 0) red[0] = rsqrtf(q / (float)D_ + EPS_);
    }
    __syncthreads();
    float r1 = red[0];
    __syncthreads();

    float x[4]; float ss2 = 0.f;
#pragma unroll
    for (int i = 0; i < 4; i++) {
        x[i] = v[i] * r1 * w1[t + 256 * i];
        ss2 += x[i] * x[i];
    }
    float w2s = warpSum(ss2);
    if (lane == 0) red[wid] = w2s;
    __syncthreads();
    if (wid == 0) {
        float q = (lane < 8) ? red[lane] : 0.f;
        q = warpSum(q);
        if (lane == 0) red[0] = rsqrtf(q / (float)D_ + EPS_);
    }
    __syncthreads();
    float r2 = red[0];
#pragma unroll
    for (int i = 0; i < 4; i++) {
        float val = x[i] * r2 * w2[t + 256 * i];
        size_t o = (size_t)token * D_ + t + 256 * i;
        __half h, l; split16(val, h, l);
        uhi[o] = h; ulo[o] = l;
    }
}

// =========================================================================
// 3-pass complex scan (CH_=128 chunks of CL_=16)
// =========================================================================
__global__ void scan_ends_kernel(const float* __restrict__ Are,
                                 const float* __restrict__ Aim,
                                 const float* __restrict__ ub,
                                 float* __restrict__ endr,
                                 float* __restrict__ endi) {
    int t = blockIdx.x * blockDim.x + threadIdx.x;
    int s = t % S_;
    int c = (t / S_) % CH_;
    int b = t / (S_ * CH_);
    float ar = Are[s], ai = Aim[s];
    float xr = 0.f, xi = 0.f;
    size_t base = (size_t)(b * L_ + c * CL_) * S2_ + s;
#pragma unroll
    for (int j = 0; j < CL_; j++) {
        size_t o = base + (size_t)j * S2_;
        float ur = ub[o], ui = ub[o + S_];
        float nr = fmaf(ar, xr, fmaf(-ai, xi, ur));
        float ni = fmaf(ar, xi, fmaf(ai, xr, ui));
        xr = nr; xi = ni;
    }
    endr[(b * CH_ + c) * S_ + s] = xr;
    endi[(b * CH_ + c) * S_ + s] = xi;
}

__global__ void scan_combine_kernel(const float* __restrict__ Are,
                                    const float* __restrict__ Aim,
                                    const float* __restrict__ endr,
                                    const float* __restrict__ endi,
                                    float* __restrict__ incr,
                                    float* __restrict__ inci) {
    int t = blockIdx.x * blockDim.x + threadIdx.x;
    if (t >= B_ * S_) return;
    int s = t % S_;
    int b = t / S_;
    float ar = Are[s], ai = Aim[s];
    float pr = 1.f, pi = 0.f;                    // A^CL_
#pragma unroll
    for (int j = 0; j < CL_; j++) {
        float nr = pr * ar - pi * ai;
        float ni = pr * ai + pi * ar;
        pr = nr; pi = ni;
    }
    float cr = 0.f, ci = 0.f;
    for (int c = 0; c < CH_; c++) {
        int idx = (b * CH_ + c) * S_ + s;
        incr[idx] = cr; inci[idx] = ci;
        float er = endr[idx], ei = endi[idx];
        float nr = fmaf(pr, cr, fmaf(-pi, ci, er));
        float ni = fmaf(pr, ci, fmaf(pi, cr, ei));
        cr = nr; ci = ni;
    }
}

__global__ void scan_final_kernel(const float* __restrict__ Are,
                                  const float* __restrict__ Aim,
                                  const float* __restrict__ incr,
                                  const float* __restrict__ inci,
                                  const float* __restrict__ ub,
                                  __half* __restrict__ xchi) {
    int t = blockIdx.x * blockDim.x + threadIdx.x;
    int s = t % S_;
    int c = (t / S_) % CH_;
    int b = t / (S_ * CH_);
    int cidx = (b * CH_ + c) * S_ + s;
    float xr = incr[cidx], xi = inci[cidx];
    float ar = Are[s], ai = Aim[s];
    size_t base = (size_t)(b * L_ + c * CL_) * S2_ + s;
#pragma unroll
    for (int j = 0; j < CL_; j++) {
        size_t o = base + (size_t)j * S2_;
        float ur = ub[o], ui = ub[o + S_];
        float nr = fmaf(ar, xr, fmaf(-ai, xi, ur));
        float ni = fmaf(ar, xi, fmaf(ai, xr, ui));
        xr = nr; xi = ni;
        xchi[o]      = __float2half(xr);
        xchi[o + S_] = __float2half(xi);
    }
}

// =========================================================================
// converters
// =========================================================================
__global__ void ccat_kernel(const float* __restrict__ Cre,
                            const float* __restrict__ Cim,
                            __half* __restrict__ hi) {
    int i = blockIdx.x * blockDim.x + threadIdx.x;
    int row = i >> 10;
    int d = i & 1023;
    float v = (row < S_) ? Cre[row * D_ + d] : -Cim[(row - S_) * D_ + d];
    hi[i] = __float2half(v);
}

__global__ void bcat_kernel(const float* __restrict__ Bre,
                            const float* __restrict__ Bim,
                            __half* __restrict__ hi,
                            __half* __restrict__ lo) {
    int i = blockIdx.x * blockDim.x + threadIdx.x;   // D_*S2_
    int d = i >> 9;
    int c = i & 511;
    float v = (c < S_) ? Bre[d * S_ + c] : Bim[d * S_ + (c - S_)];
    __half h, l; split16(v, h, l);
    hi[i] = h; lo[i] = l;
}

// FUSED: Hw -> fp16 conversion + partial gb GEMV (single pass over Hw).
__global__ void wg_fused_kernel(const float* __restrict__ Hw,
                                const float* __restrict__ Dp,
                                __half* __restrict__ whi,
                                float* __restrict__ gpart) {
    int v2 = (blockIdx.x * blockDim.x + threadIdx.x) * 2;
    if (v2 >= V_) return;
    int d0 = blockIdx.y * (D_ / GB_SLICES);
    float a0 = 0.f, a1 = 0.f;
#pragma unroll 8
    for (int j = 0; j < D_ / GB_SLICES; j++) {
        size_t o = (size_t)(d0 + j) * V_ + v2;
        float2 w = *(const float2*)(Hw + o);
        __half2 h; h.x = __float2half(w.x); h.y = __float2half(w.y);
        *(__half2*)(whi + o) = h;
        float dp = __ldg(Dp + d0 + j);
        a0 = fmaf(dp, w.x, a0);
        a1 = fmaf(dp, w.y, a1);
    }
    gpart[(size_t)blockIdx.y * V_ + v2]     = a0;
    gpart[(size_t)blockIdx.y * V_ + v2 + 1] = a1;
}

__global__ void gbias_stage2_kernel(const float* __restrict__ gpart,
                                    const float* __restrict__ Hb,
                                    float* __restrict__ gb) {
    int v = blockIdx.x * blockDim.x + threadIdx.x;
    float acc = Hb[v];
#pragma unroll
    for (int k = 0; k < GB_SLICES; k++)
        acc += gpart[(size_t)k * V_ + v];
    gb[v] = acc;
}

// =========================================================================
// Split-fp16 HMMA GEMM. CTA tile 128 x BN, BK templated, 8 warps (2m x 4n),
// 3-stage cp.async. TERMS=3/2/1 split-terms.
// ACC16: fp16-accumulate inside each BK chunk, promote to fp32 per chunk.
// =========================================================================
#define GBM 128

template<int TERMS, int BN, int BK, int ACC16>
__global__ __launch_bounds__(256)
void mma_gemm(const __half* __restrict__ Ahi,
              const __half* __restrict__ Alo,
              const __half* __restrict__ Bhi,
              const __half* __restrict__ Blo,
              float* __restrict__ Cf,
              __half* __restrict__ Chi,
              const float* __restrict__ bias,
              int Mdim, int Ndim, int Kdim) {
    constexpr int NF       = BN / 32;
    constexpr int WN       = BN / 4;
    constexpr int ASTRIDE  = (BK + 8) * 2;
    constexpr int ASPLIT   = GBM * ASTRIDE;
    constexpr int BSTRIDE  = (BN + 8) * 2;
    constexpr int BSPLIT   = BK * BSTRIDE;
    constexpr int ACPR     = BK / 8;
    constexpr int AITERS   = (GBM * ACPR) / 256;
    constexpr int CPR      = BN / 8;
    constexpr int BITERS   = (BK * CPR) / 256;
    constexpr int KS       = BK / 16;
    constexpr int A_BYTES  = (TERMS >= 2) ? 2 * ASPLIT : ASPLIT;
    constexpr int STAGE_BYTES = A_BYTES + ((TERMS == 3) ? 2 * BSPLIT : BSPLIT);
    extern __shared__ char smem[];
    uint32_t sbase = smem_to_u32(smem);
    const int tid = threadIdx.x;
    const int lane = tid & 31, wid = tid >> 5;
    const int wm = wid & 1, wn = wid >> 1;
    const int brow = blockIdx.x * GBM;
    const int bcol = blockIdx.y * BN;
    const int lda = Kdim, ldb = Ndim;
    const int niter = Kdim / BK;

    float acc[4][NF][4];
#pragma unroll
    for (int i = 0; i < 4; i++)
#pragma unroll
        for (int j = 0; j < NF; j++)
#pragma unroll
            for (int k = 0; k < 4; k++) acc[i][j][k] = 0.f;

    auto load_stage = [&](int kt, int st) {
        const int k0 = kt * BK;
        uint32_t sa = sbase + st * STAGE_BYTES;
#pragma unroll
        for (int i = 0; i < AITERS; i++) {
            int c = tid + i * 256;
            int r = c / ACPR, ch = c % ACPR;
            uint32_t dst = sa + r * ASTRIDE + ch * 16;
            size_t src = (size_t)(brow + r) * lda + k0 + ch * 8;
            cp_async16(dst, Ahi + src);
            if (TERMS >= 2) cp_async16(dst + ASPLIT, Alo + src);
        }
#pragma unroll
        for (int i = 0; i < BITERS; i++) {
            int c = tid + i * 256;
            int r = c / CPR, ch = c % CPR;
            uint32_t dst = sa + A_BYTES + r * BSTRIDE + ch * 16;
            size_t src = (size_t)(k0 + r) * ldb + bcol + ch * 8;
            cp_async16(dst, Bhi + src);
            if (TERMS == 3) cp_async16(dst + BSPLIT, Blo + src);
        }
    };

    load_stage(0, 0); CP_COMMIT();
    load_stage(1, 1); CP_COMMIT();

    for (int kt = 0; kt < niter; kt++) {
        if (kt + 2 < niter) {
            load_stage(kt + 2, (kt + 2) % 3);
            CP_COMMIT();
            CP_WAIT(2);
        } else if (kt + 2 == niter) {
            CP_WAIT(1);
        } else {
            CP_WAIT(0);
        }
        __syncthreads();

        uint32_t sa = sbase + (kt % 3) * STAGE_BYTES;

        uint32_t acc16[4][NF][2];
        if (ACC16) {
#pragma unroll
            for (int i = 0; i < 4; i++)
#pragma unroll
                for (int j = 0; j < NF; j++) {
                    acc16[i][j][0] = 0u; acc16[i][j][1] = 0u;
                }
        }

#pragma unroll
        for (int ks = 0; ks < KS; ks++) {
            uint32_t ah[4][4], al[4][4];
#pragma unroll
            for (int mf = 0; mf < 4; mf++) {
                uint32_t addr = sa + (wm * 64 + mf * 16 + (lane & 15)) * ASTRIDE
                              + ks * 32 + (lane >> 4) * 16;
                LDSM4(ah[mf][0], ah[mf][1], ah[mf][2], ah[mf][3], addr);
                if (TERMS >= 2)
                    LDSM4(al[mf][0], al[mf][1], al[mf][2], al[mf][3], addr + ASPLIT);
            }
            uint32_t bh[NF][2], bl[NF][2];
#pragma unroll
            for (int g = 0; g < NF / 2; g++) {
                uint32_t addr = sa + A_BYTES + (ks * 16 + (lane & 15)) * BSTRIDE
                              + (wn * WN + g * 16 + (lane >> 4) * 8) * 2;
                uint32_t r0, r1, r2, r3;
                LDSM4T(r0, r1, r2, r3, addr);
                bh[2 * g][0] = r0; bh[2 * g][1] = r1;
                bh[2 * g + 1][0] = r2; bh[2 * g + 1][1] = r3;
                if (TERMS == 3) {
                    LDSM4T(r0, r1, r2, r3, addr + BSPLIT);
                    bl[2 * g][0] = r0; bl[2 * g][1] = r1;
                    bl[2 * g + 1][0] = r2; bl[2 * g + 1][1] = r3;
                }
            }
#pragma unroll
            for (int mf = 0; mf < 4; mf++)
#pragma unroll
                for (int nf = 0; nf < NF; nf++) {
                    if (ACC16) {
                        MMA_F16ACC(acc16[mf][nf], ah[mf][0], ah[mf][1], ah[mf][2],
                                   ah[mf][3], bh[nf][0], bh[nf][1]);
                    } else {
                        MMA_F16(acc[mf][nf], ah[mf][0], ah[mf][1], ah[mf][2], ah[mf][3],
                                bh[nf][0], bh[nf][1]);
                        if (TERMS >= 2)
                            MMA_F16(acc[mf][nf], al[mf][0], al[mf][1], al[mf][2], al[mf][3],
                                    bh[nf][0], bh[nf][1]);
                        if (TERMS == 3)
                            MMA_F16(acc[mf][nf], ah[mf][0], ah[mf][1], ah[mf][2], ah[mf][3],
                                    bl[nf][0], bl[nf][1]);
                    }
                }
        }
        if (ACC16) {
            // promote fp16 chunk sums into persistent fp32 accumulators
#pragma unroll
            for (int mf = 0; mf < 4; mf++)
#pragma unroll
                for (int nf = 0; nf < NF; nf++) {
                    __half2 h0 = *(__half2*)&acc16[mf][nf][0];
                    __half2 h1 = *(__half2*)&acc16[mf][nf][1];
                    acc[mf][nf][0] += __low2float(h0);
                    acc[mf][nf][1] += __high2float(h0);
                    acc[mf][nf][2] += __low2float(h1);
                    acc[mf][nf][3] += __high2float(h1);
                }
        }
        __syncthreads();
    }

    if (Chi) {
#pragma unroll
        for (int mf = 0; mf < 4; mf++) {
            int r0 = brow + wm * 64 + mf * 16 + (lane >> 2);
#pragma unroll
            for (int nf = 0; nf < NF; nf++) {
                int c0 = bcol + wn * WN + nf * 8 + (lane & 3) * 2;
#pragma unroll
                for (int half_ = 0; half_ < 2; half_++) {
                    __half2 hv;
                    hv.x = __float2half(acc[mf][nf][2 * half_]);
                    hv.y = __float2half(acc[mf][nf][2 * half_ + 1]);
                    *(__half2*)(Chi + (size_t)(r0 + 8 * half_) * Ndim + c0) = hv;
                }
            }
        }
    } else {
#pragma unroll
        for (int mf = 0; mf < 4; mf++) {
            int r0 = brow + wm * 64 + mf * 16 + (lane >> 2);
#pragma unroll
            for (int nf = 0; nf < NF; nf++) {
                int c0 = bcol + wn * WN + nf * 8 + (lane & 3) * 2;
                float b0 = 0.f, b1 = 0.f;
                if (bias) { b0 = __ldg(bias + c0); b1 = __ldg(bias + c0 + 1); }
                float2 v0 = make_float2(acc[mf][nf][0] + b0, acc[mf][nf][1] + b1);
                float2 v1 = make_float2(acc[mf][nf][2] + b0, acc[mf][nf][3] + b1);
                *(float2*)(Cf + (size_t)r0 * Ndim + c0)       = v0;
                *(float2*)(Cf + (size_t)(r0 + 8) * Ndim + c0) = v1;
            }
        }
    }
}

// =========================================================================
extern "C" void kernel_launch(void* const* d_in, const int* in_sizes, int n_in,
                              void* d_out, int out_size) {
    const int*   ids = (const int*)  d_in[0];
    const float* emb = (const float*)d_in[1];
    const float* w1  = (const float*)d_in[2];
    const float* w2  = (const float*)d_in[3];
    const float* Are = (const float*)d_in[4];
    const float* Aim = (const float*)d_in[5];
    const float* Bre = (const float*)d_in[6];
    const float* Bim = (const float*)d_in[7];
    const float* Cre = (const float*)d_in[8];
    const float* Cim = (const float*)d_in[9];
    const float* Dp  = (const float*)d_in[10];
    const float* Hw  = (const float*)d_in[11];
    const float* Hb  = (const float*)d_in[12];
    float* out = (float*)d_out;

    float *ub, *endr, *endi, *incr, *inci, *gpart, *gb;
    __half *uhi, *ulo, *bchi, *bclo, *xchi, *cchi, *whi, *Ghi;
    cudaGetSymbolAddress((void**)&ub,    g_ub);
    cudaGetSymbolAddress((void**)&endr,  g_endr);
    cudaGetSymbolAddress((void**)&endi,  g_endi);
    cudaGetSymbolAddress((void**)&incr,  g_incr);
    cudaGetSymbolAddress((void**)&inci,  g_inci);
    cudaGetSymbolAddress((void**)&gpart, g_gpart);
    cudaGetSymbolAddress((void**)&uhi,   g_uhi);
    cudaGetSymbolAddress((void**)&ulo,   g_ulo);
    cudaGetSymbolAddress((void**)&bchi,  g_bchi);
    cudaGetSymbolAddress((void**)&bclo,  g_bclo);
    cudaGetSymbolAddress((void**)&xchi,  g_xchi);
    cudaGetSymbolAddress((void**)&cchi,  g_cchi);
    cudaGetSymbolAddress((void**)&whi,   g_whi);
    cudaGetSymbolAddress((void**)&Ghi,   g_Ghi);
    cudaGetSymbolAddress((void**)&gb,    g_gb);

    // smem per instantiation
    const int SM_UB = 3 * (2 * 128 * 80 + 2 * 32 * 272);   // 113664 (3-term BK32 BN128)
    const int SM_H  = 3 * (128 * 144 + 64 * 528);          // 156672 (1-term BK64 BN256)
    cudaFuncSetAttribute(mma_gemm<3,128,32,0>,
                         cudaFuncAttributeMaxDynamicSharedMemorySize, SM_UB);
    cudaFuncSetAttribute(mma_gemm<1,256,64,1>,
                         cudaFuncAttributeMaxDynamicSharedMemorySize, SM_H);

    // ---- fork a non-blocking side stream for the weight chain ----
    cudaStream_t s1 = 0;
    cudaEvent_t evF = 0, evJ = 0;
    bool fork = (cudaStreamCreateWithFlags(&s1, cudaStreamNonBlocking) == cudaSuccess);
    fork = fork && (cudaEventCreateWithFlags(&evF, cudaEventDisableTiming) == cudaSuccess);
    fork = fork && (cudaEventCreateWithFlags(&evJ, cudaEventDisableTiming) == cudaSuccess);
    cudaStream_t w = fork ? s1 : (cudaStream_t)0;

    if (fork) {
        cudaEventRecord(evF, 0);
        cudaStreamWaitEvent(w, evF, 0);
    }

    // ---- weight chain (stream w) ----
    wg_fused_kernel<<<dim3((V_ / 2 + 255) / 256, GB_SLICES), 256, 0, w>>>(
        Hw, Dp, whi, gpart);
    gbias_stage2_kernel<<<V_ / 256, 256, 0, w>>>(gpart, Hb, gb);
    ccat_kernel<<<(S2_ * D_) / 256, 256, 0, w>>>(Cre, Cim, cchi);
    // G = Ccat @ Hw  [512, 32000] (1-term, chunked fp16 accum, BN=256, BK=64)
    mma_gemm<1,256,64,1><<<dim3(S2_ / GBM, V_ / 256), 256, SM_H, w>>>(
        cchi, nullptr, whi, nullptr, nullptr, Ghi, nullptr, S2_, V_, D_);
    if (fork) cudaEventRecord(evJ, w);

    // ---- activation chain (capture stream) ----
    embed_norm_kernel<<<M_, 256>>>(ids, emb, w1, w2, uhi, ulo);
    bcat_kernel<<<(D_ * S2_) / 256, 256>>>(Bre, Bim, bchi, bclo);

    // uB = u @ Bcat  [4096, 512]  (3-term exact, fp32 out, BN=128, BK=32)
    mma_gemm<3,128,32,0><<<dim3(M_ / GBM, S2_ / 128), 256, SM_UB>>>(
        uhi, ulo, bchi, bclo, ub, nullptr, nullptr, M_, S2_, D_);

    // 3-pass complex scan -> xchi (fp16)
    scan_ends_kernel<<<(B_ * CH_ * S_) / 256, 256>>>(Are, Aim, ub, endr, endi);
    scan_combine_kernel<<<(B_ * S_ + 255) / 256, 256>>>(Are, Aim, endr, endi, incr, inci);
    scan_final_kernel<<<(B_ * CH_ * S_) / 256, 256>>>(Are, Aim, incr, inci, ub, xchi);

    // ---- join, then head ----
    if (fork) cudaStreamWaitEvent(0, evJ, 0);

    // logits = xchi @ Ghi + gb  [4096, 32000]
    // (1-term, chunked fp16 accum, BN=256, BK=64)
    mma_gemm<1,256,64,1><<<dim3(M_ / GBM, V_ / 256), 256, SM_H>>>(
        xchi, nullptr, Ghi, nullptr, out, nullptr, gb, M_, V_, S2_);
}

// round 17
// speedup vs baseline: 1.1625x; 1.1625x over previous
#include <cuda_runtime.h>
#include <cuda_fp16.h>
#include <cstdint>

#define B_  2
#define L_  2048
#define D_  1024
#define S_  256
#define V_  32000
#define M_  (B_*L_)     /* 4096 */
#define S2_ (2*S_)      /* 512  */
#define EPS_ 1e-6f

#define CH_ 128
#define CL_ (L_/CH_)    /* 16 */
#define GB_SLICES 16

// V-split for G/head overlap: 125 tiles of 256 -> 62 + 63
#define VSPLIT_TILES0 62
#define VSPLIT_COL0   (VSPLIT_TILES0 * 256)   /* 15872 */
#define VSPLIT_TILES1 (V_/256 - VSPLIT_TILES0)

// ---------------- scratch (__device__ globals; no allocs) ----------------
__device__ __align__(16) float g_ub [M_*S2_];
__device__ float g_endr[B_*CH_*S_];
__device__ float g_endi[B_*CH_*S_];
__device__ float g_incr[B_*CH_*S_];
__device__ float g_inci[B_*CH_*S_];
__device__ float g_gpart[GB_SLICES*V_];
__device__ __align__(1024) __half g_uhi[M_*D_];
__device__ __align__(1024) __half g_ulo[M_*D_];
__device__ __align__(1024) __half g_bchi[D_*S2_];
__device__ __align__(1024) __half g_bclo[D_*S2_];
__device__ __align__(1024) __half g_xchi[M_*S2_];
__device__ __align__(1024) __half g_cchi[S2_*D_];
__device__ __align__(1024) __half g_whi[(size_t)D_*V_];
__device__ __align__(1024) __half g_Ghi[(size_t)S2_*V_];
__device__ float g_gb[V_];

// ---------------- PTX helpers ------------------
__device__ __forceinline__ uint32_t smem_to_u32(const void* p) {
    uint32_t a;
    asm("{ .reg .u64 t; cvta.to.shared.u64 t, %1; cvt.u32.u64 %0, t; }"
        : "=r"(a) : "l"(p));
    return a;
}
__device__ __forceinline__ void cp_async16(uint32_t dst, const void* src) {
    asm volatile("cp.async.cg.shared.global [%0], [%1], 16;"
                 :: "r"(dst), "l"(src) : "memory");
}
#define CP_COMMIT() asm volatile("cp.async.commit_group;" ::: "memory")
#define CP_WAIT(n)  asm volatile("cp.async.wait_group %0;" :: "n"(n) : "memory")

#define LDSM4(r0,r1,r2,r3,a) \
    asm volatile("ldmatrix.sync.aligned.m8n8.x4.shared.b16 {%0,%1,%2,%3}, [%4];" \
        : "=r"(r0), "=r"(r1), "=r"(r2), "=r"(r3) : "r"(a))
#define LDSM4T(r0,r1,r2,r3,a) \
    asm volatile("ldmatrix.sync.aligned.m8n8.x4.trans.shared.b16 {%0,%1,%2,%3}, [%4];" \
        : "=r"(r0), "=r"(r1), "=r"(r2), "=r"(r3) : "r"(a))

#define MMA_F16(d, a0,a1,a2,a3, b0,b1) \
    asm volatile("mma.sync.aligned.m16n8k16.row.col.f32.f16.f16.f32 " \
        "{%0,%1,%2,%3}, {%4,%5,%6,%7}, {%8,%9}, {%0,%1,%2,%3};" \
        : "+f"((d)[0]), "+f"((d)[1]), "+f"((d)[2]), "+f"((d)[3]) \
        : "r"(a0), "r"(a1), "r"(a2), "r"(a3), "r"(b0), "r"(b1))

__inline__ __device__ float warpSum(float v) {
#pragma unroll
    for (int o = 16; o > 0; o >>= 1) v += __shfl_down_sync(0xffffffffu, v, o);
    return v;
}
__device__ __forceinline__ void split16(float v, __half& h, __half& l) {
    h = __float2half(v);
    l = __float2half(v - __half2float(h));
}

// =========================================================================
// embedding + double RMSNorm -> fp16 hi/lo
// =========================================================================
__global__ void embed_norm_kernel(const int* __restrict__ ids,
                                  const float* __restrict__ emb,
                                  const float* __restrict__ w1,
                                  const float* __restrict__ w2,
                                  __half* __restrict__ uhi,
                                  __half* __restrict__ ulo) {
    int token = blockIdx.x;
    int t = threadIdx.x;
    int id = ids[token];
    const float* e = emb + (size_t)id * D_;

    float v[4]; float ss = 0.f;
#pragma unroll
    for (int i = 0; i < 4; i++) { v[i] = e[t + 256 * i]; ss += v[i] * v[i]; }

    __shared__ float red[8];
    int lane = t & 31, wid = t >> 5;
    float w = warpSum(ss);
    if (lane == 0) red[wid] = w;
    __syncthreads();
    if (wid == 0) {
        float q = (lane < 8) ? red[lane] : 0.f;
        q = warpSum(q);
        if (lane == 0) red[0] = rsqrtf(q / (float)D_ + EPS_);
    }
    __syncthreads();
    float r1 = red[0];
    __syncthreads();

    float x[4]; float ss2 = 0.f;
#pragma unroll
    for (int i = 0; i < 4; i++) {
        x[i] = v[i] * r1 * w1[t + 256 * i];
        ss2 += x[i] * x[i];
    }
    float w2s = warpSum(ss2);
    if (lane == 0) red[wid] = w2s;
    __syncthreads();
    if (wid == 0) {
        float q = (lane < 8) ? red[lane] : 0.f;
        q = warpSum(q);
        if (lane == 0) red[0] = rsqrtf(q / (float)D_ + EPS_);
    }
    __syncthreads();
    float r2 = red[0];
#pragma unroll
    for (int i = 0; i < 4; i++) {
        float val = x[i] * r2 * w2[t + 256 * i];
        size_t o = (size_t)token * D_ + t + 256 * i;
        __half h, l; split16(val, h, l);
        uhi[o] = h; ulo[o] = l;
    }
}

// =========================================================================
// 3-pass complex scan (CH_=128 chunks of CL_=16)
// =========================================================================
__global__ void scan_ends_kernel(const float* __restrict__ Are,
                                 const float* __restrict__ Aim,
                                 const float* __restrict__ ub,
                                 float* __restrict__ endr,
                                 float* __restrict__ endi) {
    int t = blockIdx.x * blockDim.x + threadIdx.x;
    int s = t % S_;
    int c = (t / S_) % CH_;
    int b = t / (S_ * CH_);
    float ar = Are[s], ai = Aim[s];
    float xr = 0.f, xi = 0.f;
    size_t base = (size_t)(b * L_ + c * CL_) * S2_ + s;
#pragma unroll
    for (int j = 0; j < CL_; j++) {
        size_t o = base + (size_t)j * S2_;
        float ur = ub[o], ui = ub[o + S_];
        float nr = fmaf(ar, xr, fmaf(-ai, xi, ur));
        float ni = fmaf(ar, xi, fmaf(ai, xr, ui));
        xr = nr; xi = ni;
    }
    endr[(b * CH_ + c) * S_ + s] = xr;
    endi[(b * CH_ + c) * S_ + s] = xi;
}

__global__ void scan_combine_kernel(const float* __restrict__ Are,
                                    const float* __restrict__ Aim,
                                    const float* __restrict__ endr,
                                    const float* __restrict__ endi,
                                    float* __restrict__ incr,
                                    float* __restrict__ inci) {
    int t = blockIdx.x * blockDim.x + threadIdx.x;
    if (t >= B_ * S_) return;
    int s = t % S_;
    int b = t / S_;
    float ar = Are[s], ai = Aim[s];
    float pr = 1.f, pi = 0.f;                    // A^CL_
#pragma unroll
    for (int j = 0; j < CL_; j++) {
        float nr = pr * ar - pi * ai;
        float ni = pr * ai + pi * ar;
        pr = nr; pi = ni;
    }
    float cr = 0.f, ci = 0.f;
    for (int c = 0; c < CH_; c++) {
        int idx = (b * CH_ + c) * S_ + s;
        incr[idx] = cr; inci[idx] = ci;
        float er = endr[idx], ei = endi[idx];
        float nr = fmaf(pr, cr, fmaf(-pi, ci, er));
        float ni = fmaf(pr, ci, fmaf(pi, cr, ei));
        cr = nr; ci = ni;
    }
}

__global__ void scan_final_kernel(const float* __restrict__ Are,
                                  const float* __restrict__ Aim,
                                  const float* __restrict__ incr,
                                  const float* __restrict__ inci,
                                  const float* __restrict__ ub,
                                  __half* __restrict__ xchi) {
    int t = blockIdx.x * blockDim.x + threadIdx.x;
    int s = t % S_;
    int c = (t / S_) % CH_;
    int b = t / (S_ * CH_);
    int cidx = (b * CH_ + c) * S_ + s;
    float xr = incr[cidx], xi = inci[cidx];
    float ar = Are[s], ai = Aim[s];
    size_t base = (size_t)(b * L_ + c * CL_) * S2_ + s;
#pragma unroll
    for (int j = 0; j < CL_; j++) {
        size_t o = base + (size_t)j * S2_;
        float ur = ub[o], ui = ub[o + S_];
        float nr = fmaf(ar, xr, fmaf(-ai, xi, ur));
        float ni = fmaf(ar, xi, fmaf(ai, xr, ui));
        xr = nr; xi = ni;
        xchi[o]      = __float2half(xr);
        xchi[o + S_] = __float2half(xi);
    }
}

// =========================================================================
// converters
// =========================================================================
__global__ void ccat_kernel(const float* __restrict__ Cre,
                            const float* __restrict__ Cim,
                            __half* __restrict__ hi) {
    int i = blockIdx.x * blockDim.x + threadIdx.x;
    int row = i >> 10;
    int d = i & 1023;
    float v = (row < S_) ? Cre[row * D_ + d] : -Cim[(row - S_) * D_ + d];
    hi[i] = __float2half(v);
}

__global__ void bcat_kernel(const float* __restrict__ Bre,
                            const float* __restrict__ Bim,
                            __half* __restrict__ hi,
                            __half* __restrict__ lo) {
    int i = blockIdx.x * blockDim.x + threadIdx.x;   // D_*S2_
    int d = i >> 9;
    int c = i & 511;
    float v = (c < S_) ? Bre[d * S_ + c] : Bim[d * S_ + (c - S_)];
    __half h, l; split16(v, h, l);
    hi[i] = h; lo[i] = l;
}

// FUSED: Hw -> fp16 conversion + partial gb GEMV (single pass over Hw).
__global__ void wg_fused_kernel(const float* __restrict__ Hw,
                                const float* __restrict__ Dp,
                                __half* __restrict__ whi,
                                float* __restrict__ gpart) {
    int v2 = (blockIdx.x * blockDim.x + threadIdx.x) * 2;
    if (v2 >= V_) return;
    int d0 = blockIdx.y * (D_ / GB_SLICES);
    float a0 = 0.f, a1 = 0.f;
#pragma unroll 8
    for (int j = 0; j < D_ / GB_SLICES; j++) {
        size_t o = (size_t)(d0 + j) * V_ + v2;
        float2 w = *(const float2*)(Hw + o);
        __half2 h; h.x = __float2half(w.x); h.y = __float2half(w.y);
        *(__half2*)(whi + o) = h;
        float dp = __ldg(Dp + d0 + j);
        a0 = fmaf(dp, w.x, a0);
        a1 = fmaf(dp, w.y, a1);
    }
    gpart[(size_t)blockIdx.y * V_ + v2]     = a0;
    gpart[(size_t)blockIdx.y * V_ + v2 + 1] = a1;
}

__global__ void gbias_stage2_kernel(const float* __restrict__ gpart,
                                    const float* __restrict__ Hb,
                                    float* __restrict__ gb) {
    int v = blockIdx.x * blockDim.x + threadIdx.x;
    float acc = Hb[v];
#pragma unroll
    for (int k = 0; k < GB_SLICES; k++)
        acc += gpart[(size_t)k * V_ + v];
    gb[v] = acc;
}

// =========================================================================
// Split-fp16 HMMA GEMM (round-12 proven config). CTA tile 128 x BN, BK
// templated, 8 warps (2m x 4n), 3-stage cp.async. TERMS=3/2/1 split-terms.
// =========================================================================
#define GBM 128

template<int TERMS, int BN, int BK>
__global__ __launch_bounds__(256, 1)
void mma_gemm(const __half* __restrict__ Ahi,
              const __half* __restrict__ Alo,
              const __half* __restrict__ Bhi,
              const __half* __restrict__ Blo,
              float* __restrict__ Cf,
              __half* __restrict__ Chi,
              const float* __restrict__ bias,
              int Mdim, int Ndim, int Kdim) {
    constexpr int NF       = BN / 32;
    constexpr int WN       = BN / 4;
    constexpr int ASTRIDE  = (BK + 8) * 2;
    constexpr int ASPLIT   = GBM * ASTRIDE;
    constexpr int BSTRIDE  = (BN + 8) * 2;
    constexpr int BSPLIT   = BK * BSTRIDE;
    constexpr int ACPR     = BK / 8;
    constexpr int AITERS   = (GBM * ACPR) / 256;
    constexpr int CPR      = BN / 8;
    constexpr int BITERS   = (BK * CPR) / 256;
    constexpr int KS       = BK / 16;
    constexpr int A_BYTES  = (TERMS >= 2) ? 2 * ASPLIT : ASPLIT;
    constexpr int STAGE_BYTES = A_BYTES + ((TERMS == 3) ? 2 * BSPLIT : BSPLIT);
    extern __shared__ char smem[];
    uint32_t sbase = smem_to_u32(smem);
    const int tid = threadIdx.x;
    const int lane = tid & 31, wid = tid >> 5;
    const int wm = wid & 1, wn = wid >> 1;
    const int brow = blockIdx.x * GBM;
    const int bcol = blockIdx.y * BN;
    const int lda = Kdim, ldb = Ndim;
    const int niter = Kdim / BK;

    float acc[4][NF][4];
#pragma unroll
    for (int i = 0; i < 4; i++)
#pragma unroll
        for (int j = 0; j < NF; j++)
#pragma unroll
            for (int k = 0; k < 4; k++) acc[i][j][k] = 0.f;

    auto load_stage = [&](int kt, int st) {
        const int k0 = kt * BK;
        uint32_t sa = sbase + st * STAGE_BYTES;
#pragma unroll
        for (int i = 0; i < AITERS; i++) {
            int c = tid + i * 256;
            int r = c / ACPR, ch = c % ACPR;
            uint32_t dst = sa + r * ASTRIDE + ch * 16;
            size_t src = (size_t)(brow + r) * lda + k0 + ch * 8;
            cp_async16(dst, Ahi + src);
            if (TERMS >= 2) cp_async16(dst + ASPLIT, Alo + src);
        }
#pragma unroll
        for (int i = 0; i < BITERS; i++) {
            int c = tid + i * 256;
            int r = c / CPR, ch = c % CPR;
            uint32_t dst = sa + A_BYTES + r * BSTRIDE + ch * 16;
            size_t src = (size_t)(k0 + r) * ldb + bcol + ch * 8;
            cp_async16(dst, Bhi + src);
            if (TERMS == 3) cp_async16(dst + BSPLIT, Blo + src);
        }
    };

    load_stage(0, 0); CP_COMMIT();
    load_stage(1, 1); CP_COMMIT();

    for (int kt = 0; kt < niter; kt++) {
        if (kt + 2 < niter) {
            load_stage(kt + 2, (kt + 2) % 3);
            CP_COMMIT();
            CP_WAIT(2);
        } else if (kt + 2 == niter) {
            CP_WAIT(1);
        } else {
            CP_WAIT(0);
        }
        __syncthreads();

        uint32_t sa = sbase + (kt % 3) * STAGE_BYTES;
#pragma unroll
        for (int ks = 0; ks < KS; ks++) {
            uint32_t ah[4][4], al[4][4];
#pragma unroll
            for (int mf = 0; mf < 4; mf++) {
                uint32_t addr = sa + (wm * 64 + mf * 16 + (lane & 15)) * ASTRIDE
                              + ks * 32 + (lane >> 4) * 16;
                LDSM4(ah[mf][0], ah[mf][1], ah[mf][2], ah[mf][3], addr);
                if (TERMS >= 2)
                    LDSM4(al[mf][0], al[mf][1], al[mf][2], al[mf][3], addr + ASPLIT);
            }
            uint32_t bh[NF][2], bl[NF][2];
#pragma unroll
            for (int g = 0; g < NF / 2; g++) {
                uint32_t addr = sa + A_BYTES + (ks * 16 + (lane & 15)) * BSTRIDE
                              + (wn * WN + g * 16 + (lane >> 4) * 8) * 2;
                uint32_t r0, r1, r2, r3;
                LDSM4T(r0, r1, r2, r3, addr);
                bh[2 * g][0] = r0; bh[2 * g][1] = r1;
                bh[2 * g + 1][0] = r2; bh[2 * g + 1][1] = r3;
                if (TERMS == 3) {
                    LDSM4T(r0, r1, r2, r3, addr + BSPLIT);
                    bl[2 * g][0] = r0; bl[2 * g][1] = r1;
                    bl[2 * g + 1][0] = r2; bl[2 * g + 1][1] = r3;
                }
            }
#pragma unroll
            for (int mf = 0; mf < 4; mf++)
#pragma unroll
                for (int nf = 0; nf < NF; nf++) {
                    MMA_F16(acc[mf][nf], ah[mf][0], ah[mf][1], ah[mf][2], ah[mf][3],
                            bh[nf][0], bh[nf][1]);
                    if (TERMS >= 2)
                        MMA_F16(acc[mf][nf], al[mf][0], al[mf][1], al[mf][2], al[mf][3],
                                bh[nf][0], bh[nf][1]);
                    if (TERMS == 3)
                        MMA_F16(acc[mf][nf], ah[mf][0], ah[mf][1], ah[mf][2], ah[mf][3],
                                bl[nf][0], bl[nf][1]);
                }
        }
        __syncthreads();
    }

    if (Chi) {
#pragma unroll
        for (int mf = 0; mf < 4; mf++) {
            int r0 = brow + wm * 64 + mf * 16 + (lane >> 2);
#pragma unroll
            for (int nf = 0; nf < NF; nf++) {
                int c0 = bcol + wn * WN + nf * 8 + (lane & 3) * 2;
#pragma unroll
                for (int half_ = 0; half_ < 2; half_++) {
                    __half2 hv;
                    hv.x = __float2half(acc[mf][nf][2 * half_]);
                    hv.y = __float2half(acc[mf][nf][2 * half_ + 1]);
                    *(__half2*)(Chi + (size_t)(r0 + 8 * half_) * Ndim + c0) = hv;
                }
            }
        }
    } else {
#pragma unroll
        for (int mf = 0; mf < 4; mf++) {
            int r0 = brow + wm * 64 + mf * 16 + (lane >> 2);
#pragma unroll
            for (int nf = 0; nf < NF; nf++) {
                int c0 = bcol + wn * WN + nf * 8 + (lane & 3) * 2;
                float b0 = 0.f, b1 = 0.f;
                if (bias) { b0 = __ldg(bias + c0); b1 = __ldg(bias + c0 + 1); }
                float2 v0 = make_float2(acc[mf][nf][0] + b0, acc[mf][nf][1] + b1);
                float2 v1 = make_float2(acc[mf][nf][2] + b0, acc[mf][nf][3] + b1);
                *(float2*)(Cf + (size_t)r0 * Ndim + c0)       = v0;
                *(float2*)(Cf + (size_t)(r0 + 8) * Ndim + c0) = v1;
            }
        }
    }
}

// =========================================================================
extern "C" void kernel_launch(void* const* d_in, const int* in_sizes, int n_in,
                              void* d_out, int out_size) {
    const int*   ids = (const int*)  d_in[0];
    const float* emb = (const float*)d_in[1];
    const float* w1  = (const float*)d_in[2];
    const float* w2  = (const float*)d_in[3];
    const float* Are = (const float*)d_in[4];
    const float* Aim = (const float*)d_in[5];
    const float* Bre = (const float*)d_in[6];
    const float* Bim = (const float*)d_in[7];
    const float* Cre = (const float*)d_in[8];
    const float* Cim = (const float*)d_in[9];
    const float* Dp  = (const float*)d_in[10];
    const float* Hw  = (const float*)d_in[11];
    const float* Hb  = (const float*)d_in[12];
    float* out = (float*)d_out;

    float *ub, *endr, *endi, *incr, *inci, *gpart, *gb;
    __half *uhi, *ulo, *bchi, *bclo, *xchi, *cchi, *whi, *Ghi;
    cudaGetSymbolAddress((void**)&ub,    g_ub);
    cudaGetSymbolAddress((void**)&endr,  g_endr);
    cudaGetSymbolAddress((void**)&endi,  g_endi);
    cudaGetSymbolAddress((void**)&incr,  g_incr);
    cudaGetSymbolAddress((void**)&inci,  g_inci);
    cudaGetSymbolAddress((void**)&gpart, g_gpart);
    cudaGetSymbolAddress((void**)&uhi,   g_uhi);
    cudaGetSymbolAddress((void**)&ulo,   g_ulo);
    cudaGetSymbolAddress((void**)&bchi,  g_bchi);
    cudaGetSymbolAddress((void**)&bclo,  g_bclo);
    cudaGetSymbolAddress((void**)&xchi,  g_xchi);
    cudaGetSymbolAddress((void**)&cchi,  g_cchi);
    cudaGetSymbolAddress((void**)&whi,   g_whi);
    cudaGetSymbolAddress((void**)&Ghi,   g_Ghi);
    cudaGetSymbolAddress((void**)&gb,    g_gb);

    // smem per instantiation (round-12 proven)
    const int SM_UB = 3 * (2 * 128 * 80 + 2 * 32 * 272);   // 113664 (3-term BK32 BN128)
    const int SM_G  = 3 * (128 * 144 + 64 * 528);          // 156672 (1-term BK64 BN256)
    cudaFuncSetAttribute(mma_gemm<3,128,32>,
                         cudaFuncAttributeMaxDynamicSharedMemorySize, SM_UB);
    cudaFuncSetAttribute(mma_gemm<1,256,64>,
                         cudaFuncAttributeMaxDynamicSharedMemorySize, SM_G);

    // ---- fork a non-blocking side stream for the weight chain ----
    cudaStream_t s1 = 0;
    cudaEvent_t evF = 0, evG0 = 0, evJ = 0;
    bool fork = (cudaStreamCreateWithFlags(&s1, cudaStreamNonBlocking) == cudaSuccess);
    fork = fork && (cudaEventCreateWithFlags(&evF, cudaEventDisableTiming) == cudaSuccess);
    fork = fork && (cudaEventCreateWithFlags(&evG0, cudaEventDisableTiming) == cudaSuccess);
    fork = fork && (cudaEventCreateWithFlags(&evJ, cudaEventDisableTiming) == cudaSuccess);
    cudaStream_t w = fork ? s1 : (cudaStream_t)0;

    if (fork) {
        cudaEventRecord(evF, 0);
        cudaStreamWaitEvent(w, evF, 0);
    }

    // ---- weight chain (stream w) ----
    wg_fused_kernel<<<dim3((V_ / 2 + 255) / 256, GB_SLICES), 256, 0, w>>>(
        Hw, Dp, whi, gpart);
    gbias_stage2_kernel<<<V_ / 256, 256, 0, w>>>(gpart, Hb, gb);
    ccat_kernel<<<(S2_ * D_) / 256, 256, 0, w>>>(Cre, Cim, cchi);
    // G = Ccat @ Hw  [512, 32000]  (1-term fp16, BN=256, BK=64) in 2 V-halves
    mma_gemm<1,256,64><<<dim3(S2_ / GBM, VSPLIT_TILES0), 256, SM_G, w>>>(
        cchi, nullptr, whi, nullptr, nullptr, Ghi, nullptr, S2_, V_, D_);
    if (fork) cudaEventRecord(evG0, w);
    mma_gemm<1,256,64><<<dim3(S2_ / GBM, VSPLIT_TILES1), 256, SM_G, w>>>(
        cchi, nullptr, whi + VSPLIT_COL0, nullptr, nullptr, Ghi + VSPLIT_COL0,
        nullptr, S2_, V_, D_);
    if (fork) cudaEventRecord(evJ, w);

    // ---- activation chain (capture stream) ----
    embed_norm_kernel<<<M_, 256>>>(ids, emb, w1, w2, uhi, ulo);
    bcat_kernel<<<(D_ * S2_) / 256, 256>>>(Bre, Bim, bchi, bclo);

    // uB = u @ Bcat  [4096, 512]  (3-term exact, fp32 out, BN=128, BK=32)
    mma_gemm<3,128,32><<<dim3(M_ / GBM, S2_ / 128), 256, SM_UB>>>(
        uhi, ulo, bchi, bclo, ub, nullptr, nullptr, M_, S2_, D_);

    // 3-pass complex scan -> xchi (fp16)
    scan_ends_kernel<<<(B_ * CH_ * S_) / 256, 256>>>(Are, Aim, ub, endr, endi);
    scan_combine_kernel<<<(B_ * S_ + 255) / 256, 256>>>(Are, Aim, endr, endi, incr, inci);
    scan_final_kernel<<<(B_ * CH_ * S_) / 256, 256>>>(Are, Aim, incr, inci, ub, xchi);

    // ---- head in 2 V-halves: half-0 starts as soon as G-half-0 is done ----
    if (fork) cudaStreamWaitEvent(0, evG0, 0);
    mma_gemm<1,256,64><<<dim3(M_ / GBM, VSPLIT_TILES0), 256, SM_G>>>(
        xchi, nullptr, Ghi, nullptr, out, nullptr, gb, M_, V_, S2_);
    if (fork) cudaStreamWaitEvent(0, evJ, 0);
    mma_gemm<1,256,64><<<dim3(M_ / GBM, VSPLIT_TILES1), 256, SM_G>>>(
        xchi, nullptr, Ghi + VSPLIT_COL0, nullptr, out + VSPLIT_COL0, nullptr,
        gb + VSPLIT_COL0, M_, V_, S2_);
}